// round 6
// baseline (speedup 1.0000x reference)
#include <cuda_runtime.h>
#include <cuda_bf16.h>

// <Z_0> after RY·RX on all qubits + CNOT chain reduces analytically to the
// qubit-0 gate only (CNOTs preserve the q0 bit; gates on q1..q15 are
// block-unitary and preserve per-block norms):
//   A = ||u||^2 - ||v||^2,  S = sum(u * conj(v))   (u = top half, v = bottom)
//   <Z_0> = cos^2(t) * A - 2 sin(t) * (Re S + cos(t) * Im S)
//
// R5 (= R4 re-run after infra failure): stream-length-preserving 148-block
// decomposition. Evidence R0/R1/R3: achieved HBM BW tracks DRAM stream length
// (128KB:57% > 16KB:52% > 3.5KB:48%). Flatten the (row, idx) space, give each
// of 148 blocks ONE contiguous ~7086-float4 chunk (~110KB streams), so all
// SMs are active AND streams stay long. A chunk crosses <=2 row boundaries;
// per-row partial slots + closed-form contributor counts give a deterministic
// fixed-order combine; counter reset keeps graph replays clean.

#ifndef QN
#define QN 16
#endif
static constexpr int D      = 1 << QN;       // 65536
static constexpr int HALF   = D >> 1;        // 32768 floats per half-row
static constexpr int HALF4  = HALF >> 2;     // 8192 float4 per half-row (2^13)
static constexpr int LOG_H4 = 13;
static constexpr int NT     = 1024;
static constexpr int NBLK   = 148;
static constexpr int MAXROW = 1024;
static constexpr int SLOTS  = 4;             // max contributing blocks per row

__device__ float    g_part[MAXROW * SLOTS * 3];
__device__ unsigned g_cnt[MAXROW];           // zero at load; reset each launch

__inline__ __device__ float warp_sum(float v) {
    #pragma unroll
    for (int o = 16; o > 0; o >>= 1)
        v += __shfl_down_sync(0xffffffffu, v, o);
    return v;
}

__device__ __forceinline__ void accum(const float4 a, const float4 b,
                                      const float4 c, const float4 d,
                                      float& A, float& P, float& Q) {
    A += (a.x*a.x + c.x*c.x) - (b.x*b.x + d.x*d.x);
    A += (a.y*a.y + c.y*c.y) - (b.y*b.y + d.y*d.y);
    A += (a.z*a.z + c.z*c.z) - (b.z*b.z + d.z*d.z);
    A += (a.w*a.w + c.w*c.w) - (b.w*b.w + d.w*d.w);
    P += a.x*b.x + c.x*d.x;
    P += a.y*b.y + c.y*d.y;
    P += a.z*b.z + c.z*d.z;
    P += a.w*b.w + c.w*d.w;
    Q += c.x*b.x - a.x*d.x;
    Q += c.y*b.y - a.y*d.y;
    Q += c.z*b.z - a.z*d.z;
    Q += c.w*b.w - a.w*d.w;
}

__global__ __launch_bounds__(NT, 1)
void zexp_kernel(const float* __restrict__ re,
                 const float* __restrict__ im,
                 const float* __restrict__ thetas,
                 float* __restrict__ out,
                 int G, int chunk)
{
    __shared__ float sA[NT / 32], sP[NT / 32], sQ[NT / 32];

    const int lane = threadIdx.x & 31;
    const int wid  = threadIdx.x >> 5;

    int g0 = blockIdx.x * chunk;
    const int g1 = min(g0 + chunk, G);

    while (g0 < g1) {                               // block-uniform loop
        const int row      = g0 >> LOG_H4;
        const int row_base = row << LOG_H4;
        const int s_end    = min(g1, row_base + HALF4);  // segment [g0, s_end)
        const int l0       = g0 - row_base;              // local float4 offsets
        const int l1       = s_end - row_base;
        const int len      = l1 - l0;
        const int full     = (len / NT) * NT;            // unguarded portion

        const size_t base = (size_t)row * D;
        const float4* __restrict__ ru = (const float4*)(re + base);
        const float4* __restrict__ rv = (const float4*)(re + base + HALF);
        const float4* __restrict__ iu = (const float4*)(im + base);
        const float4* __restrict__ iv = (const float4*)(im + base + HALF);

        float A = 0.f, P = 0.f, Q = 0.f;

        // hot loop: no per-iteration guard, 4x4 independent LDG.128 batched
        int i = l0 + threadIdx.x;
        const int iend_full = l0 + full;
        #pragma unroll 4
        for (; i < iend_full; i += NT)
            accum(ru[i], rv[i], iu[i], iv[i], A, P, Q);
        // guarded tail (< NT elements)
        if (i < l1)
            accum(ru[i], rv[i], iu[i], iv[i], A, P, Q);

        A = warp_sum(A);
        P = warp_sum(P);
        Q = warp_sum(Q);
        if (lane == 0) { sA[wid] = A; sP[wid] = P; sQ[wid] = Q; }
        __syncthreads();

        if (threadIdx.x == 0) {
            float tA = 0.f, tP = 0.f, tQ = 0.f;
            #pragma unroll
            for (int w = 0; w < NT / 32; ++w) { tA += sA[w]; tP += sP[w]; tQ += sQ[w]; }

            // slot index for this block within this row, and contributor count
            const int first = row_base / chunk;
            const int last  = (row_base + HALF4 - 1) / chunk;
            const int nb    = last - first + 1;                 // <= SLOTS
            const int j     = (int)blockIdx.x - first;

            float* slot = &g_part[(row * SLOTS + j) * 3];
            slot[0] = tA; slot[1] = tP; slot[2] = tQ;
            __threadfence();

            const unsigned old = atomicAdd(&g_cnt[row], 1u);
            if (old == (unsigned)(nb - 1)) {
                __threadfence();
                float fA = 0.f, fP = 0.f, fQ = 0.f;
                const float* p = &g_part[row * SLOTS * 3];
                for (int s = 0; s < nb; ++s) {    // fixed order: deterministic
                    fA += p[s * 3 + 0];
                    fP += p[s * 3 + 1];
                    fQ += p[s * 3 + 2];
                }
                const float t  = thetas[0];
                const float ct = cosf(t);
                const float st = sinf(t);
                out[row] = ct * ct * fA - 2.f * st * (fP + ct * fQ);
                atomicExch(&g_cnt[row], 0u);      // clean for next graph replay
            }
        }
        __syncthreads();    // sA reuse safe before next segment
        g0 = s_end;
    }
}

extern "C" void kernel_launch(void* const* d_in, const int* in_sizes, int n_in,
                              void* d_out, int out_size)
{
    const float* re     = (const float*)d_in[0];  // states_re (B, 65536)
    const float* im     = (const float*)d_in[1];  // states_im (B, 65536)
    const float* thetas = (const float*)d_in[2];  // (16,)
    float* out = (float*)d_out;                   // (B,)

    const int B = in_sizes[0] / D;                // 128
    const int G = B * HALF4;                      // 1,048,576 float4 positions
    int nblk = NBLK;
    int chunk = (G + nblk - 1) / nblk;            // 7086
    // guarantee a row never spans more than SLOTS chunks
    while (chunk * (SLOTS - 1) < HALF4) { chunk *= 2; }
    nblk = (G + chunk - 1) / chunk;

    zexp_kernel<<<nblk, NT>>>(re, im, thetas, out, G, chunk);
}

// round 7
// speedup vs baseline: 1.0049x; 1.0049x over previous
#include <cuda_runtime.h>
#include <cuda_bf16.h>

// <Z_0> after RY·RX on all qubits + CNOT chain reduces analytically to the
// qubit-0 gate only (CNOTs preserve the q0 bit; gates on q1..q15 are
// block-unitary and preserve per-block norms):
//   A = ||u||^2 - ||v||^2,  S = sum(u * conj(v))   (u = top half, v = bottom)
//   <Z_0> = cos^2(t) * A - 2 sin(t) * (Re S + cos(t) * Im S)
//
// R6: R0's proven shape (static fully-unrolled, guard-free inner loop, 1024
// threads -- the variable that correlates with DRAM% across R0/R1/R3/R5 is
// compiled load batching, not stream length) + the one fix R0 needed: 2 blocks
// per row so all 148 SMs are active (256 CTAs). Static 4-iteration body keeps
// 16 independent LDG.128 per thread front-batched. Two-slot deterministic
// per-row combine; counter reset keeps graph replays clean.

#ifndef QN
#define QN 16
#endif
static constexpr int D     = 1 << QN;     // 65536
static constexpr int HALF  = D >> 1;      // 32768 floats per half-row
static constexpr int HALF4 = HALF >> 2;   // 8192 float4 per half-row
static constexpr int SPLIT = 2;
static constexpr int NT    = 1024;
static constexpr int CHUNK4 = HALF4 / SPLIT;   // 4096 float4 per block
static constexpr int ITERS  = CHUNK4 / NT;     // 4 (compile-time, exact)
static constexpr int MAXB   = 512;

__device__ float    g_part[MAXB * SPLIT * 3];
__device__ unsigned g_cnt[MAXB];          // zero at load; reset each launch

__inline__ __device__ float warp_sum(float v) {
    #pragma unroll
    for (int o = 16; o > 0; o >>= 1)
        v += __shfl_down_sync(0xffffffffu, v, o);
    return v;
}

__global__ __launch_bounds__(NT)
void zexp_kernel(const float* __restrict__ re,
                 const float* __restrict__ im,
                 const float* __restrict__ thetas,
                 float* __restrict__ out)
{
    const int row = blockIdx.x;
    const int sp  = blockIdx.y;
    const size_t base = (size_t)row * D;
    const int coff = sp * CHUNK4;

    const float4* __restrict__ ru = (const float4*)(re + base)        + coff;
    const float4* __restrict__ rv = (const float4*)(re + base + HALF) + coff;
    const float4* __restrict__ iu = (const float4*)(im + base)        + coff;
    const float4* __restrict__ iv = (const float4*)(im + base + HALF) + coff;

    float A = 0.f, P = 0.f, Q = 0.f;

    // static, fully unrolled, guard-free: 16 independent LDG.128 per thread
    #pragma unroll
    for (int k = 0; k < ITERS; ++k) {
        const int idx = threadIdx.x + k * NT;
        const float4 a = ru[idx];   // u_r
        const float4 b = rv[idx];   // v_r
        const float4 c = iu[idx];   // u_i
        const float4 d = iv[idx];   // v_i

        A += (a.x*a.x + c.x*c.x) - (b.x*b.x + d.x*d.x);
        A += (a.y*a.y + c.y*c.y) - (b.y*b.y + d.y*d.y);
        A += (a.z*a.z + c.z*c.z) - (b.z*b.z + d.z*d.z);
        A += (a.w*a.w + c.w*c.w) - (b.w*b.w + d.w*d.w);

        P += a.x*b.x + c.x*d.x;
        P += a.y*b.y + c.y*d.y;
        P += a.z*b.z + c.z*d.z;
        P += a.w*b.w + c.w*d.w;

        Q += c.x*b.x - a.x*d.x;
        Q += c.y*b.y - a.y*d.y;
        Q += c.z*b.z - a.z*d.z;
        Q += c.w*b.w - a.w*d.w;
    }

    A = warp_sum(A);
    P = warp_sum(P);
    Q = warp_sum(Q);

    __shared__ float sA[NT / 32], sP[NT / 32], sQ[NT / 32];
    const int lane = threadIdx.x & 31;
    const int wid  = threadIdx.x >> 5;
    if (lane == 0) { sA[wid] = A; sP[wid] = P; sQ[wid] = Q; }
    __syncthreads();

    if (threadIdx.x == 0) {
        float tA = 0.f, tP = 0.f, tQ = 0.f;
        #pragma unroll
        for (int w = 0; w < NT / 32; ++w) { tA += sA[w]; tP += sP[w]; tQ += sQ[w]; }

        float* slot = &g_part[(row * SPLIT + sp) * 3];
        slot[0] = tA; slot[1] = tP; slot[2] = tQ;
        __threadfence();

        const unsigned old = atomicAdd(&g_cnt[row], 1u);
        if (old == SPLIT - 1) {
            __threadfence();
            const float* p = &g_part[row * SPLIT * 3];
            float fA = 0.f, fP = 0.f, fQ = 0.f;
            #pragma unroll
            for (int s = 0; s < SPLIT; ++s) {   // fixed order: deterministic
                fA += p[s * 3 + 0];
                fP += p[s * 3 + 1];
                fQ += p[s * 3 + 2];
            }
            const float t  = thetas[0];
            const float ct = cosf(t);
            const float st = sinf(t);
            out[row] = ct * ct * fA - 2.f * st * (fP + ct * fQ);
            atomicExch(&g_cnt[row], 0u);        // clean for next graph replay
        }
    }
}

extern "C" void kernel_launch(void* const* d_in, const int* in_sizes, int n_in,
                              void* d_out, int out_size)
{
    const float* re     = (const float*)d_in[0];  // states_re (B, 65536)
    const float* im     = (const float*)d_in[1];  // states_im (B, 65536)
    const float* thetas = (const float*)d_in[2];  // (16,)
    float* out = (float*)d_out;                   // (B,)

    const int B = in_sizes[0] / D;                // 128
    dim3 grid(B, SPLIT);
    zexp_kernel<<<grid, NT>>>(re, im, thetas, out);
}

// round 8
// speedup vs baseline: 1.2111x; 1.2053x over previous
#include <cuda_runtime.h>
#include <cuda_bf16.h>

// <Z_0> after RY·RX on all qubits + CNOT chain reduces analytically to the
// qubit-0 gate only (CNOTs preserve the q0 bit; gates on q1..q15 are
// block-unitary and preserve per-block norms):
//   A = ||u||^2 - ||v||^2,  S = sum(u * conj(v))   (u = top half, v = bottom)
//   <Z_0> = cos^2(t) * A - 2 sin(t) * (Re S + cos(t) * Im S)
//
// R7: R0's proven config restored EXACTLY (grid=128 x 1024 threads,
// launch_bounds(1024,1) => 64-reg budget, static fully-unrolled guard-free
// loop -- every deviation from this in R1/R3/R5/R6 lost 8-20% of bandwidth),
// plus two intra-loop refinements that keep the launch shape:
//   1. explicit distance-1 software pipeline (double-buffered float4 regs)
//      so >=8 LDG.128 per thread are in flight by construction;
//   2. split accumulators to halve the FFMA dependency chain.
// Timed R0 hit 6.06 TB/s (76% of spec) from 128 SMs; this run probes the
// last intra-loop headroom and otherwise confirms the roofline.

#ifndef QN
#define QN 16
#endif
static constexpr int D     = 1 << QN;     // 65536
static constexpr int HALF  = D >> 1;      // 32768 floats per half-row
static constexpr int HALF4 = HALF >> 2;   // 8192 float4 per half-row
static constexpr int NTHREADS = 1024;
static constexpr int ITERS = HALF4 / NTHREADS;  // 8 (compile-time, exact)

__inline__ __device__ float warp_sum(float v) {
    #pragma unroll
    for (int o = 16; o > 0; o >>= 1)
        v += __shfl_down_sync(0xffffffffu, v, o);
    return v;
}

__global__ __launch_bounds__(NTHREADS, 1)
void zexp_kernel(const float* __restrict__ re,
                 const float* __restrict__ im,
                 const float* __restrict__ thetas,
                 float* __restrict__ out)
{
    const int row = blockIdx.x;
    const size_t base = (size_t)row * D;

    const float4* __restrict__ ru = (const float4*)(re + base);          // u_r
    const float4* __restrict__ rv = (const float4*)(re + base + HALF);   // v_r
    const float4* __restrict__ iu = (const float4*)(im + base);          // u_i
    const float4* __restrict__ iv = (const float4*)(im + base + HALF);   // v_i

    const int t = threadIdx.x;

    // prologue: iteration 0 loads
    float4 a = ru[t], b = rv[t], c = iu[t], d = iv[t];

    float A0 = 0.f, A1 = 0.f, P0 = 0.f, P1 = 0.f, Q0 = 0.f, Q1 = 0.f;

    #pragma unroll
    for (int k = 0; k < ITERS; ++k) {
        float4 na, nb, nc, nd;
        if (k + 1 < ITERS) {                 // compile-time guard (unrolled)
            const int idx = t + (k + 1) * NTHREADS;
            na = ru[idx]; nb = rv[idx]; nc = iu[idx]; nd = iv[idx];
        }

        // split accumulators: x,y -> set0, z,w -> set1 (half-length chains)
        A0 += (a.x*a.x + c.x*c.x) - (b.x*b.x + d.x*d.x);
        A0 += (a.y*a.y + c.y*c.y) - (b.y*b.y + d.y*d.y);
        A1 += (a.z*a.z + c.z*c.z) - (b.z*b.z + d.z*d.z);
        A1 += (a.w*a.w + c.w*c.w) - (b.w*b.w + d.w*d.w);

        P0 += a.x*b.x + c.x*d.x;
        P0 += a.y*b.y + c.y*d.y;
        P1 += a.z*b.z + c.z*d.z;
        P1 += a.w*b.w + c.w*d.w;

        Q0 += c.x*b.x - a.x*d.x;
        Q0 += c.y*b.y - a.y*d.y;
        Q1 += c.z*b.z - a.z*d.z;
        Q1 += c.w*b.w - a.w*d.w;

        if (k + 1 < ITERS) { a = na; b = nb; c = nc; d = nd; }
    }

    float A = A0 + A1, P = P0 + P1, Q = Q0 + Q1;

    A = warp_sum(A);
    P = warp_sum(P);
    Q = warp_sum(Q);

    __shared__ float sA[NTHREADS / 32];
    __shared__ float sP[NTHREADS / 32];
    __shared__ float sQ[NTHREADS / 32];

    const int lane = threadIdx.x & 31;
    const int wid  = threadIdx.x >> 5;
    if (lane == 0) { sA[wid] = A; sP[wid] = P; sQ[wid] = Q; }
    __syncthreads();

    if (wid == 0) {
        A = (lane < NTHREADS / 32) ? sA[lane] : 0.f;
        P = (lane < NTHREADS / 32) ? sP[lane] : 0.f;
        Q = (lane < NTHREADS / 32) ? sQ[lane] : 0.f;
        A = warp_sum(A);
        P = warp_sum(P);
        Q = warp_sum(Q);
        if (lane == 0) {
            const float t0 = thetas[0];
            const float ct = cosf(t0);
            const float st = sinf(t0);
            out[row] = ct * ct * A - 2.f * st * (P + ct * Q);
        }
    }
}

extern "C" void kernel_launch(void* const* d_in, const int* in_sizes, int n_in,
                              void* d_out, int out_size)
{
    const float* re     = (const float*)d_in[0];  // states_re (B, 65536)
    const float* im     = (const float*)d_in[1];  // states_im (B, 65536)
    const float* thetas = (const float*)d_in[2];  // (16,)
    float* out = (float*)d_out;                   // (B,)

    const int B = in_sizes[0] / D;                // 128
    zexp_kernel<<<B, NTHREADS>>>(re, im, thetas, out);
}